// round 6
// baseline (speedup 1.0000x reference)
#include <cuda_runtime.h>
#include <cuda_bf16.h>
#include <cstdint>

// HungarianMatcher cost computation, block-diagonal only.
// Shapes: BS=16, Q=1000, NC=80, T=100, NI=8
// Output: C_diag (BS,Q,T) followed by ioa_diag (BS,Q,NI), f32.
//
// Structure: phase 1 precomputes 2*focal_class_cost for ALL (q, class) pairs
// of the block's q-tile (dense, coalesced, all lanes) + per-q pred-box derived
// values into smem; phase 2 is a short pure-FMA loop (L1 + GIoU) with no MUFU
// chain except one rcp.

#define BSZ 16
#define QN  1000
#define NC  80
#define TN  100
#define NIN 8
#define QPB 20   // q rows per block
#define PQW 12   // floats per q in the pq table (padded for float4 access)

__global__ __launch_bounds__(128, 10)
void matcher_kernel(const float* __restrict__ logits,
                    const float* __restrict__ pboxes,
                    const float* __restrict__ tboxes,
                    const float* __restrict__ iboxes,
                    const float* __restrict__ img,
                    const float* __restrict__ img_tgt,
                    const int*   __restrict__ tids,
                    float* __restrict__ outC,
                    float* __restrict__ outIoa)
{
    __shared__ float scc[QPB * NC];     // 2*focal class cost, [q_local][class]
    __shared__ float spq[QPB * PQW];    // per-q: raw box(4), norm box(4), parea

    const int b    = blockIdx.y;
    const int q0   = blockIdx.x * QPB;
    const int lane = threadIdx.x;   // 0..99 -> targets, 100..107 -> ign boxes

    const bool isC   = (lane < TN);
    const bool isIoa = (lane >= TN) && (lane < TN + NIN);

    // ---------------- phase 1a: focal class cost table (all lanes) ----------
    // scc[q][c] = 2*(pos - neg) with a single log:
    //   e = exp(-x); p = 1/(1+e); -log(p) = log(1+e) = L; -log(1-p) = x + L
    {
        const float* gl = logits + (size_t)(b * QN + q0) * NC;
        #pragma unroll 4
        for (int idx = lane; idx < QPB * NC; idx += 128) {
            const float x   = gl[idx];          // fully coalesced
            const float e   = __expf(-x);
            const float s   = 1.f + e;
            const float p   = __frcp_rn(s);
            const float L   = __logf(s);
            const float omp = 1.f - p;
            const float pos = 0.25f * omp * omp * L;
            const float neg = 0.75f * p * p * (x + L);
            scc[idx] = 2.f * (pos - neg);
        }
    }

    // ---------------- phase 1b: per-q pred box table (lanes 0..QPB-1) -------
    if (lane < QPB) {
        const float* im = img + b * 4;
        const float4 pb = *reinterpret_cast<const float4*>(
                              pboxes + (size_t)(b * QN + q0 + lane) * 4);
        float* row = spq + lane * PQW;
        row[0] = pb.x; row[1] = pb.y; row[2] = pb.z; row[3] = pb.w;
        row[4] = pb.x * __frcp_rn(im[0]);
        row[5] = pb.y * __frcp_rn(im[1]);
        row[6] = pb.z * __frcp_rn(im[2]);
        row[7] = pb.w * __frcp_rn(im[3]);
        row[8] = (pb.z - pb.x) * (pb.w - pb.y);   // parea
    }

    // ---------------- per-lane target / ignore data -------------------------
    float tx0 = 0.f, ty0 = 0.f, tx1 = 0.f, ty1 = 0.f;
    float tnx0 = 0.f, tny0 = 0.f, tnx1 = 0.f, tny1 = 0.f;
    float tarea = 0.f;
    int   cls = 0;

    if (isC) {
        const int ti = b * TN + lane;
        const float4 tb = *reinterpret_cast<const float4*>(tboxes + ti * 4);
        tx0 = tb.x; ty0 = tb.y; tx1 = tb.z; ty1 = tb.w;
        const float4 it = *reinterpret_cast<const float4*>(img_tgt + ti * 4);
        tnx0 = tx0 * __frcp_rn(it.x);
        tny0 = ty0 * __frcp_rn(it.y);
        tnx1 = tx1 * __frcp_rn(it.z);
        tny1 = ty1 * __frcp_rn(it.w);
        tarea = (tx1 - tx0) * (ty1 - ty0);
        cls = tids[ti];
    } else if (isIoa) {
        const int ii = b * NIN + (lane - TN);
        const float4 ib = *reinterpret_cast<const float4*>(iboxes + ii * 4);
        tx0 = ib.x; ty0 = ib.y; tx1 = ib.z; ty1 = ib.w;
    }

    __syncthreads();

    // ---------------- phase 2: hot loop (short FMA chain, 1 rcp) ------------
    float* outC_lane   = outC   + (size_t)(b * QN + q0) * TN  + lane;
    float* outIoa_lane = outIoa + (size_t)(b * QN + q0) * NIN + (lane - TN);

    #pragma unroll 5
    for (int i = 0; i < QPB; ++i) {
        const float* row = spq + i * PQW;
        const float4 praw = *reinterpret_cast<const float4*>(row);      // bcast
        const float px0 = praw.x, py0 = praw.y, px1 = praw.z, py1 = praw.w;

        if (isC) {
            const float4 pn = *reinterpret_cast<const float4*>(row + 4); // bcast
            const float parea = row[8];                                  // bcast
            const float cc2   = scc[i * NC + cls];

            // L1 bbox cost on normalized boxes
            const float cb = fabsf(pn.x - tnx0) + fabsf(pn.y - tny0)
                           + fabsf(pn.z - tnx1) + fabsf(pn.w - tny1);

            // GIoU with a single reciprocal:
            // giou = inter/uni + uni/enc - 1 = (inter*enc + uni*uni)/(uni*enc) - 1
            const float ixw = fminf(px1, tx1) - fmaxf(px0, tx0);
            const float iyw = fminf(py1, ty1) - fmaxf(py0, ty0);
            const float inter = fmaxf(ixw, 0.f) * fmaxf(iyw, 0.f);
            const float uni = parea + tarea - inter;
            const float exw = fmaxf(px1, tx1) - fminf(px0, tx0);
            const float eyw = fmaxf(py1, ty1) - fminf(py0, ty0);
            const float enc = fmaxf(exw, 0.f) * fmaxf(eyw, 0.f);
            const float r   = __frcp_rn(uni * enc);
            // 2*giou + 2 = (inter*enc + uni*uni) * (2r)
            const float g2  = fmaf(inter * enc + uni * uni, 2.f * r, -2.f);

            // C = 5*cb + cc2 - g2   (cc2 = 2*cost_class, g2 = 2*giou)
            outC_lane[i * TN] = fmaf(5.f, cb, cc2 - g2);
        } else if (isIoa) {
            const float parea = row[8];
            const float ixw = fminf(px1, tx1) - fmaxf(px0, tx0);
            const float iyw = fminf(py1, ty1) - fmaxf(py0, ty0);
            const float inter = fmaxf(ixw, 0.f) * fmaxf(iyw, 0.f);
            outIoa_lane[i * NIN] = inter * __frcp_rn(parea);
        }
    }
}

extern "C" void kernel_launch(void* const* d_in, const int* in_sizes, int n_in,
                              void* d_out, int out_size)
{
    const float* logits  = (const float*)d_in[0];
    const float* pboxes  = (const float*)d_in[1];
    const float* tboxes  = (const float*)d_in[2];
    const float* iboxes  = (const float*)d_in[3];
    const float* img     = (const float*)d_in[4];
    const float* img_tgt = (const float*)d_in[5];
    const int*   tids    = (const int*)d_in[6];

    float* outC   = (float*)d_out;
    float* outIoa = (float*)d_out + (size_t)BSZ * QN * TN;

    dim3 grid(QN / QPB, BSZ);
    matcher_kernel<<<grid, 128>>>(logits, pboxes, tboxes, iboxes,
                                  img, img_tgt, tids, outC, outIoa);
}

// round 7
// speedup vs baseline: 1.0764x; 1.0764x over previous
#include <cuda_runtime.h>
#include <cuda_bf16.h>
#include <cstdint>

// HungarianMatcher cost computation, block-diagonal only.
// Shapes: BS=16, Q=1000, NC=80, T=100, NI=8
// Output: C_diag (BS,Q,T) followed by ioa_diag (BS,Q,NI), f32.
//
// Mapping: lanes 0..99 -> targets (C cost), 100..107 -> ignore boxes (ioa),
// loop over QPB q-rows. All loop-invariant memory (logit gathers + pred
// boxes) staged through smem via cp.async so registers stay <= 42, allowing
// 12 resident blocks/SM (75% occupancy ceiling).

#define BSZ 16
#define QN  1000
#define NC  80
#define TN  100
#define NIN 8
#define QPB 10   // q rows per block

__global__ __launch_bounds__(128, 12)
void matcher_kernel(const float* __restrict__ logits,
                    const float* __restrict__ pboxes,
                    const float* __restrict__ tboxes,
                    const float* __restrict__ iboxes,
                    const float* __restrict__ img,
                    const float* __restrict__ img_tgt,
                    const int*   __restrict__ tids,
                    float* __restrict__ outC,
                    float* __restrict__ outIoa)
{
    __shared__ float  slog[QPB][128];   // staged logit gathers, [q_iter][lane]
    __shared__ float4 spb[QPB];         // staged pred boxes

    const int b    = blockIdx.y;
    const int q0   = blockIdx.x * QPB;
    const int lane = threadIdx.x;   // 0..99 -> targets, 100..107 -> ign boxes

    const bool isC   = (lane < TN);
    const bool isIoa = (lane >= TN) && (lane < TN + NIN);

    // ---- stage pred boxes (lanes 0..QPB-1, one 16B cp.async each) ----
    if (lane < QPB) {
        uint32_t saddr = (uint32_t)__cvta_generic_to_shared(&spb[lane]);
        asm volatile("cp.async.ca.shared.global [%0], [%1], 16;\n"
                     :: "r"(saddr),
                        "l"(pboxes + (size_t)(b * QN + q0 + lane) * 4));
    }

    // ---- per-lane target / ignore data (registers) ----
    float tx0 = 0.f, ty0 = 0.f, tx1 = 0.f, ty1 = 0.f;
    float tnx0 = 0.f, tny0 = 0.f, tnx1 = 0.f, tny1 = 0.f;
    float tarea = 0.f;

    if (isC) {
        const int ti = b * TN + lane;
        const float4 tb = *reinterpret_cast<const float4*>(tboxes + ti * 4);
        tx0 = tb.x; ty0 = tb.y; tx1 = tb.z; ty1 = tb.w;
        const float4 it = *reinterpret_cast<const float4*>(img_tgt + ti * 4);
        tnx0 = tx0 * __frcp_rn(it.x);
        tny0 = ty0 * __frcp_rn(it.y);
        tnx1 = tx1 * __frcp_rn(it.z);
        tny1 = ty1 * __frcp_rn(it.w);
        tarea = (tx1 - tx0) * (ty1 - ty0);
    } else if (isIoa) {
        const int ii = b * NIN + (lane - TN);
        const float4 ib = *reinterpret_cast<const float4*>(iboxes + ii * 4);
        tx0 = ib.x; ty0 = ib.y; tx1 = ib.z; ty1 = ib.w;
    }

    // ---- stage all QPB logit gathers via cp.async (MLP=10, no reg cost) ----
    if (isC) {
        const int cls = tids[b * TN + lane];
        const float* gl = logits + (size_t)(b * QN + q0) * NC + cls;
        #pragma unroll
        for (int i = 0; i < QPB; ++i) {
            uint32_t saddr = (uint32_t)__cvta_generic_to_shared(&slog[i][lane]);
            asm volatile("cp.async.ca.shared.global [%0], [%1], 4;\n"
                         :: "r"(saddr), "l"(gl + i * NC));
        }
    }
    asm volatile("cp.async.commit_group;\n");

    // per-batch image normalization (reciprocals) — overlap with copies
    const float* im = img + b * 4;
    const float iw0 = __frcp_rn(im[0]);
    const float ih0 = __frcp_rn(im[1]);
    const float iw1 = __frcp_rn(im[2]);
    const float ih1 = __frcp_rn(im[3]);

    asm volatile("cp.async.wait_group 0;\n" ::: "memory");
    __syncthreads();   // spb written by lanes 0..9, read by all

    float* outC_lane   = outC   + (size_t)(b * QN + q0) * TN  + lane;
    float* outIoa_lane = outIoa + (size_t)(b * QN + q0) * NIN + (lane - TN);

    #pragma unroll
    for (int i = 0; i < QPB; ++i) {
        const float4 pb = spb[i];          // uniform LDS.128 broadcast
        const float px0 = pb.x, py0 = pb.y, px1 = pb.z, py1 = pb.w;
        const float parea = (px1 - px0) * (py1 - py0);

        if (isC) {
            // ---- focal class cost with a single log ----
            // e = exp(-x); p = 1/(1+e); -log(p) = log(1+e) = L; -log(1-p) = x + L
            const float x   = slog[i][lane];
            const float e   = __expf(-x);
            const float s   = 1.f + e;
            const float p   = __frcp_rn(s);
            const float L   = __logf(s);
            const float omp = 1.f - p;
            const float pos = 0.25f * omp * omp * L;
            const float neg = 0.75f * p * p * (x + L);
            const float cclass = pos - neg;

            // ---- L1 bbox cost on normalized boxes ----
            const float cb = fabsf(px0 * iw0 - tnx0)
                           + fabsf(py0 * ih0 - tny0)
                           + fabsf(px1 * iw1 - tnx1)
                           + fabsf(py1 * ih1 - tny1);

            // ---- GIoU with a single reciprocal ----
            const float ixw = fminf(px1, tx1) - fmaxf(px0, tx0);
            const float iyw = fminf(py1, ty1) - fmaxf(py0, ty0);
            const float inter = fmaxf(ixw, 0.f) * fmaxf(iyw, 0.f);
            const float uni = parea + tarea - inter;
            const float exw = fmaxf(px1, tx1) - fminf(px0, tx0);
            const float eyw = fmaxf(py1, ty1) - fminf(py0, ty0);
            const float enc = fmaxf(exw, 0.f) * fmaxf(eyw, 0.f);
            // giou = inter/uni + uni/enc - 1 = (inter*enc + uni*uni)/(uni*enc) - 1
            const float r    = __frcp_rn(uni * enc);
            const float giou = fmaf(inter * enc + uni * uni, r, -1.f);

            const float C = fmaf(5.f, cb, fmaf(2.f, cclass, -2.f * giou));
            outC_lane[i * TN] = C;
        } else if (isIoa) {
            const float ixw = fminf(px1, tx1) - fmaxf(px0, tx0);
            const float iyw = fminf(py1, ty1) - fmaxf(py0, ty0);
            const float inter = fmaxf(ixw, 0.f) * fmaxf(iyw, 0.f);
            outIoa_lane[i * NIN] = inter * __frcp_rn(parea);
        }
    }
}

extern "C" void kernel_launch(void* const* d_in, const int* in_sizes, int n_in,
                              void* d_out, int out_size)
{
    const float* logits  = (const float*)d_in[0];
    const float* pboxes  = (const float*)d_in[1];
    const float* tboxes  = (const float*)d_in[2];
    const float* iboxes  = (const float*)d_in[3];
    const float* img     = (const float*)d_in[4];
    const float* img_tgt = (const float*)d_in[5];
    const int*   tids    = (const int*)d_in[6];

    float* outC   = (float*)d_out;
    float* outIoa = (float*)d_out + (size_t)BSZ * QN * TN;

    dim3 grid(QN / QPB, BSZ);
    matcher_kernel<<<grid, 128>>>(logits, pboxes, tboxes, iboxes,
                                  img, img_tgt, tids, outC, outIoa);
}

// round 8
// speedup vs baseline: 1.2457x; 1.1572x over previous
#include <cuda_runtime.h>
#include <cuda_bf16.h>
#include <cstdint>

// HungarianMatcher cost computation, block-diagonal only.
// Shapes: BS=16, Q=1000, NC=80, T=100, NI=8
// Output: C_diag (BS,Q,T) followed by ioa_diag (BS,Q,NI), f32.
//
// Phase 1: dense 2*focal_class_cost for the block's QPB x NC tile (coalesced,
//          all 128 lanes, 5 independent passes) + per-q pred-box table.
// Phase 2: hot loop is pure FMA + 2 LDS + 1 rcp per element (no exp/log).

#define BSZ 16
#define QN  1000
#define NC  80
#define TN  100
#define NIN 8
#define QPB 8    // q rows per block; 125 blocks cover Q=1000 exactly
#define PQW 12   // floats per q row in spq (padded for float4 access)

__global__ __launch_bounds__(128, 12)
void matcher_kernel(const float* __restrict__ logits,
                    const float* __restrict__ pboxes,
                    const float* __restrict__ tboxes,
                    const float* __restrict__ iboxes,
                    const float* __restrict__ img,
                    const float* __restrict__ img_tgt,
                    const int*   __restrict__ tids,
                    float* __restrict__ outC,
                    float* __restrict__ outIoa)
{
    __shared__ float scc[QPB * NC];    // 2*focal class cost, [q_local][class]
    __shared__ float spq[QPB * PQW];   // per-q: raw box(4), norm box(4), parea

    const int b    = blockIdx.y;
    const int q0   = blockIdx.x * QPB;
    const int lane = threadIdx.x;   // 0..99 -> targets, 100..107 -> ign boxes

    const bool isC   = (lane < TN);
    const bool isIoa = (lane >= TN) && (lane < TN + NIN);

    // ---------------- phase 1a: dense focal table (all lanes) ---------------
    // scc[q][c] = 2*(pos - neg), single log:
    //   e = exp(-x); p = 1/(1+e); -log(p) = log(1+e) = L; -log(1-p) = x + L
    {
        const float* gl = logits + (size_t)(b * QN + q0) * NC;
        #pragma unroll
        for (int k = 0; k < (QPB * NC) / 128; ++k) {      // exactly 5 passes
            const int idx   = k * 128 + lane;
            const float x   = __ldg(gl + idx);            // fully coalesced
            const float e   = __expf(-x);
            const float s   = 1.f + e;
            const float p   = __frcp_rn(s);
            const float L   = __logf(s);
            const float omp = 1.f - p;
            const float pos = 0.25f * omp * omp * L;
            const float neg = 0.75f * p * p * (x + L);
            scc[idx] = 2.f * (pos - neg);
        }
    }

    // ---------------- phase 1b: per-q pred box table (lanes 0..QPB-1) -------
    if (lane < QPB) {
        const float* im = img + b * 4;
        const float4 pb = *reinterpret_cast<const float4*>(
                              pboxes + (size_t)(b * QN + q0 + lane) * 4);
        float* row = spq + lane * PQW;
        row[0] = pb.x; row[1] = pb.y; row[2] = pb.z; row[3] = pb.w;
        row[4] = pb.x * __frcp_rn(im[0]);
        row[5] = pb.y * __frcp_rn(im[1]);
        row[6] = pb.z * __frcp_rn(im[2]);
        row[7] = pb.w * __frcp_rn(im[3]);
        row[8] = (pb.z - pb.x) * (pb.w - pb.y);   // parea
    }

    // ---------------- per-lane target / ignore data (registers) -------------
    float tx0 = 0.f, ty0 = 0.f, tx1 = 0.f, ty1 = 0.f;
    float tnx0 = 0.f, tny0 = 0.f, tnx1 = 0.f, tny1 = 0.f;
    float tarea = 0.f;
    int   cls = 0;

    if (isC) {
        const int ti = b * TN + lane;
        const float4 tb = *reinterpret_cast<const float4*>(tboxes + ti * 4);
        tx0 = tb.x; ty0 = tb.y; tx1 = tb.z; ty1 = tb.w;
        const float4 it = *reinterpret_cast<const float4*>(img_tgt + ti * 4);
        tnx0 = tx0 * __frcp_rn(it.x);
        tny0 = ty0 * __frcp_rn(it.y);
        tnx1 = tx1 * __frcp_rn(it.z);
        tny1 = ty1 * __frcp_rn(it.w);
        tarea = (tx1 - tx0) * (ty1 - ty0);
        cls = tids[ti];
    } else if (isIoa) {
        const int ii = b * NIN + (lane - TN);
        const float4 ib = *reinterpret_cast<const float4*>(iboxes + ii * 4);
        tx0 = ib.x; ty0 = ib.y; tx1 = ib.z; ty1 = ib.w;
    }

    __syncthreads();

    // ---------------- phase 2: hot loop (short FMA chain, 1 rcp) ------------
    float* outC_lane   = outC   + (size_t)(b * QN + q0) * TN  + lane;
    float* outIoa_lane = outIoa + (size_t)(b * QN + q0) * NIN + (lane - TN);

    #pragma unroll
    for (int i = 0; i < QPB; ++i) {
        const float* row = spq + i * PQW;

        if (isC) {
            const float4 praw = *reinterpret_cast<const float4*>(row);       // bcast
            const float4 pn   = *reinterpret_cast<const float4*>(row + 4);   // bcast
            const float parea = row[8];                                      // bcast
            const float cc2   = scc[i * NC + cls];
            const float px0 = praw.x, py0 = praw.y, px1 = praw.z, py1 = praw.w;

            // L1 bbox cost on normalized boxes
            const float cb = fabsf(pn.x - tnx0) + fabsf(pn.y - tny0)
                           + fabsf(pn.z - tnx1) + fabsf(pn.w - tny1);

            // GIoU with a single reciprocal:
            // giou = inter/uni + uni/enc - 1 = (inter*enc + uni*uni)/(uni*enc) - 1
            const float ixw = fminf(px1, tx1) - fmaxf(px0, tx0);
            const float iyw = fminf(py1, ty1) - fmaxf(py0, ty0);
            const float inter = fmaxf(ixw, 0.f) * fmaxf(iyw, 0.f);
            const float uni = parea + tarea - inter;
            const float exw = fmaxf(px1, tx1) - fminf(px0, tx0);
            const float eyw = fmaxf(py1, ty1) - fminf(py0, ty0);
            const float enc = fmaxf(exw, 0.f) * fmaxf(eyw, 0.f);
            const float r   = __frcp_rn(uni * enc);
            // g2 = 2*giou
            const float g2  = fmaf(inter * enc + uni * uni, 2.f * r, -2.f);

            // C = 5*cb + cc2 - g2   (cc2 = 2*cost_class)
            outC_lane[i * TN] = fmaf(5.f, cb, cc2 - g2);
        } else if (isIoa) {
            const float4 praw = *reinterpret_cast<const float4*>(row);
            const float parea = row[8];
            const float px0 = praw.x, py0 = praw.y, px1 = praw.z, py1 = praw.w;
            const float ixw = fminf(px1, tx1) - fmaxf(px0, tx0);
            const float iyw = fminf(py1, ty1) - fmaxf(py0, ty0);
            const float inter = fmaxf(ixw, 0.f) * fmaxf(iyw, 0.f);
            outIoa_lane[i * NIN] = inter * __frcp_rn(parea);
        }
    }
}

extern "C" void kernel_launch(void* const* d_in, const int* in_sizes, int n_in,
                              void* d_out, int out_size)
{
    const float* logits  = (const float*)d_in[0];
    const float* pboxes  = (const float*)d_in[1];
    const float* tboxes  = (const float*)d_in[2];
    const float* iboxes  = (const float*)d_in[3];
    const float* img     = (const float*)d_in[4];
    const float* img_tgt = (const float*)d_in[5];
    const int*   tids    = (const int*)d_in[6];

    float* outC   = (float*)d_out;
    float* outIoa = (float*)d_out + (size_t)BSZ * QN * TN;

    dim3 grid(QN / QPB, BSZ);   // 125 x 16 = 2000 blocks
    matcher_kernel<<<grid, 128>>>(logits, pboxes, tboxes, iboxes,
                                  img, img_tgt, tids, outC, outIoa);
}